// round 15
// baseline (speedup 1.0000x reference)
#include <cuda_runtime.h>
#include <cuda_bf16.h>
#include <cstdint>

#define DIM 1024

// G = [Re(PE); Im(PE)] (1024 x 1024), stored column-of-G, i-contiguous:
//   g_Gh[m][i] = bf16hi(G[i][m]),  g_Gl[m][i] = bf16lo
__device__ __nv_bfloat16 g_Gh[DIM * DIM];
__device__ __nv_bfloat16 g_Gl[DIM * DIM];
__device__ float         g_y [DIM * DIM];      // y = x + x^T
__device__ float         g_partials[392];
__device__ unsigned      g_cnt;                // zero-init; reset by last CTA

__device__ __forceinline__ uint32_t smem_to_u32(const void* p) {
    uint32_t a;
    asm("{ .reg .u64 t; cvta.to.shared.u64 t, %1; cvt.u32.u64 %0, t; }" : "=r"(a) : "l"(p));
    return a;
}

#define CP_ASYNC16(dst, src) \
    asm volatile("cp.async.ca.shared.global [%0], [%1], 16;" :: "r"(dst), "l"(src) : "memory")
#define CP_COMMIT() asm volatile("cp.async.commit_group;" ::: "memory")
#define CP_WAIT2()  asm volatile("cp.async.wait_group 2;" ::: "memory")
#define CP_WAIT1()  asm volatile("cp.async.wait_group 1;" ::: "memory")
#define CP_WAIT0()  asm volatile("cp.async.wait_group 0;" ::: "memory")

#define LDSM_X4(r, a) \
    asm volatile("ldmatrix.sync.aligned.m8n8.x4.shared.b16 {%0,%1,%2,%3}, [%4];" \
        : "=r"((r)[0]), "=r"((r)[1]), "=r"((r)[2]), "=r"((r)[3]) : "r"(a))

#define MMA_BF16(d, a, b) \
    asm volatile("mma.sync.aligned.m16n8k16.row.col.f32.bf16.bf16.f32 " \
        "{%0,%1,%2,%3},{%4,%5,%6,%7},{%8,%9},{%0,%1,%2,%3};" \
        : "+f"((d)[0]), "+f"((d)[1]), "+f"((d)[2]), "+f"((d)[3]) \
        : "r"((a)[0]), "r"((a)[1]), "r"((a)[2]), "r"((a)[3]), \
          "r"((b)[0]), "r"((b)[1]))

__device__ __forceinline__ float2 cmul(float2 a, float2 b) {
    return make_float2(a.x * b.x - a.y * b.y, a.x * b.y + a.y * b.x);
}
__device__ __forceinline__ float2 cadd(float2 a, float2 b) {
    return make_float2(a.x + b.x, a.y + b.y);
}

// Layout rotation: new-layout index u holds state phi(u); old bits 9..6 land
// in u bits 3..0 (slot + low lane bits -> shfl/local reachable).
__device__ __forceinline__ int phi_map(int u)  { return ((u & 15) << 6) | (u >> 4); }
__device__ __forceinline__ int phi_inv(int s)  { return ((s & 63) << 4) | (s >> 6); }
__device__ __forceinline__ int pad_i(int i)    { return i + (i >> 6); }

// CNOT chain q=1..9 source index for output state s.
__device__ __forceinline__ int cnot_src(int s) {
    int j = s;
    #pragma unroll
    for (int q = 9; q >= 1; q--) {
        int pc = 10 - q, pt = 9 - q;
        if ((j >> pc) & 1) j ^= (1 << pt);
    }
    return j;
}

// ---------------------------------------------------------------------------
// Build kernel: register-resident statevector, 4 columns/block, commuting
// gates reordered so only 2 smem round-trips per sign pass:
//   Phase A: gates on state bits 5..1 (shfl) and 0 (local)      [std layout]
//   Phase B: one smem rotation to new layout (bits 9..6 -> 3..0)
//   Phase C: gates on old bits 9..6 via shfl (bits 3..1) + local (bit 0)
//   Phase D: one smem gather composing inverse rotation + CNOT permutation
//            (on the final pass, also the bit-4 projection + bf16 split)
//   blocks [256,512): 64x64 tiles of y = x + x^T.
// ---------------------------------------------------------------------------
__global__ __launch_bounds__(512) void build_kernel(const float* __restrict__ w,
                                                    const float* __restrict__ x) {
    __shared__ float2 sg[2][10][4];
    __shared__ __align__(16) float2 sbuf[4][1040];   // 1024 + row padding
    int t = threadIdx.x;

    if (blockIdx.x >= 256) {
        // ---- y = x + x^T, 64x64 tile ----
        float (*tl)[65] = (float (*)[65])sbuf;       // 16640 B < 33280 B
        int id = blockIdx.x - 256;
        int a0c = (id >> 4) * 64, b0c = (id & 15) * 64;
        int tx = t & 63, ty = t >> 6;
        #pragma unroll
        for (int r = 0; r < 8; r++)
            tl[tx][ty + 8 * r] = x[(b0c + ty + 8 * r) * DIM + a0c + tx];
        __syncthreads();
        #pragma unroll
        for (int r = 0; r < 8; r++) {
            int a = a0c + ty + 8 * r;
            g_y[a * DIM + b0c + tx] = x[a * DIM + b0c + tx] + tl[ty + 8 * r][tx];
        }
        return;
    }

    if (t < 20) {
        int s = t / 10, q = t % 10;
        float sign = s ? -1.f : 1.f;
        const float WM = 0.63245553203367586f;  // sqrt(2/5)
        float hx = 0.5f * sign * w[q]      * WM;
        float hy = 0.5f * sign * w[q + 10] * WM;
        float hz = 0.5f * sign * w[q + 20] * WM;
        float cx, sx, cy, sy, cz, sz;
        sincosf(hx, &sx, &cx);
        sincosf(hy, &sy, &cy);
        sincosf(hz, &sz, &cz);
        float2 T00 = make_float2( cy * cx,  sy * sx);
        float2 T01 = make_float2(-sy * cx, -cy * sx);
        float2 T10 = make_float2( sy * cx, -cy * sx);
        float2 T11 = make_float2( cy * cx, -sy * sx);
        float2 e0 = make_float2(cz, -sz);
        float2 e1 = make_float2(cz,  sz);
        sg[s][q][0] = cmul(e0, T00);
        sg[s][q][1] = cmul(e0, T01);
        sg[s][q][2] = cmul(e1, T10);
        sg[s][q][3] = cmul(e1, T11);
    }

    int col0 = blockIdx.x * 4;
    float2 r0[4], r1[4];
    #pragma unroll
    for (int c = 0; c < 4; c++) {
        int col = col0 + c;
        r0[c] = make_float2((2 * t == col)     ? 1.f : 0.f, 0.f);
        r1[c] = make_float2((2 * t + 1 == col) ? 1.f : 0.f, 0.f);
    }

    // Loop-invariant gather indices
    int rdB0 = pad_i(phi_map(2 * t)), rdB1 = pad_i(phi_map(2 * t + 1));
    int rdD0 = pad_i(phi_inv(cnot_src(2 * t)));
    int rdD1 = pad_i(phi_inv(cnot_src(2 * t + 1)));
    int stp  = ((t & ~15) << 1) | 16 | (t & 15);       // projected state
    int rdP  = pad_i(phi_inv(cnot_src(stp)));
    int wr0  = pad_i(2 * t), wr1 = pad_i(2 * t + 1);

    __syncthreads();                                   // sg visible

    #pragma unroll
    for (int s = 0; s < 2; s++) {
        // ---- Phase A: state bits 5..1 via shfl, bit 0 local (q = 4..9) ----
        #pragma unroll
        for (int p = 5; p >= 1; p--) {
            float2 g00 = sg[s][9 - p][0], g01 = sg[s][9 - p][1];
            float2 g10 = sg[s][9 - p][2], g11 = sg[s][9 - p][3];
            int m = 1 << (p - 1);
            int b = (t >> (p - 1)) & 1;
            #pragma unroll
            for (int c = 0; c < 4; c++) {
                float2 o0, o1;
                o0.x = __shfl_xor_sync(0xffffffffu, r0[c].x, m);
                o0.y = __shfl_xor_sync(0xffffffffu, r0[c].y, m);
                o1.x = __shfl_xor_sync(0xffffffffu, r1[c].x, m);
                o1.y = __shfl_xor_sync(0xffffffffu, r1[c].y, m);
                if (b == 0) {
                    r0[c] = cadd(cmul(g00, r0[c]), cmul(g01, o0));
                    r1[c] = cadd(cmul(g00, r1[c]), cmul(g01, o1));
                } else {
                    r0[c] = cadd(cmul(g10, o0), cmul(g11, r0[c]));
                    r1[c] = cadd(cmul(g10, o1), cmul(g11, r1[c]));
                }
            }
        }
        {
            float2 g00 = sg[s][9][0], g01 = sg[s][9][1];
            float2 g10 = sg[s][9][2], g11 = sg[s][9][3];
            #pragma unroll
            for (int c = 0; c < 4; c++) {
                float2 n0 = cadd(cmul(g00, r0[c]), cmul(g01, r1[c]));
                float2 n1 = cadd(cmul(g10, r0[c]), cmul(g11, r1[c]));
                r0[c] = n0; r1[c] = n1;
            }
        }
        // ---- Phase B: rotate layout ----
        #pragma unroll
        for (int c = 0; c < 4; c++) { sbuf[c][wr0] = r0[c]; sbuf[c][wr1] = r1[c]; }
        __syncthreads();
        #pragma unroll
        for (int c = 0; c < 4; c++) { r0[c] = sbuf[c][rdB0]; r1[c] = sbuf[c][rdB1]; }
        __syncthreads();
        // ---- Phase C: old bits 9..6 = new bits 3..0 (q = 3-k) ----
        #pragma unroll
        for (int k = 3; k >= 1; k--) {
            float2 g00 = sg[s][3 - k][0], g01 = sg[s][3 - k][1];
            float2 g10 = sg[s][3 - k][2], g11 = sg[s][3 - k][3];
            int m = 1 << (k - 1);
            int b = (t >> (k - 1)) & 1;
            #pragma unroll
            for (int c = 0; c < 4; c++) {
                float2 o0, o1;
                o0.x = __shfl_xor_sync(0xffffffffu, r0[c].x, m);
                o0.y = __shfl_xor_sync(0xffffffffu, r0[c].y, m);
                o1.x = __shfl_xor_sync(0xffffffffu, r1[c].x, m);
                o1.y = __shfl_xor_sync(0xffffffffu, r1[c].y, m);
                if (b == 0) {
                    r0[c] = cadd(cmul(g00, r0[c]), cmul(g01, o0));
                    r1[c] = cadd(cmul(g00, r1[c]), cmul(g01, o1));
                } else {
                    r0[c] = cadd(cmul(g10, o0), cmul(g11, r0[c]));
                    r1[c] = cadd(cmul(g10, o1), cmul(g11, r1[c]));
                }
            }
        }
        {
            float2 g00 = sg[s][3][0], g01 = sg[s][3][1];   // old bit 6 = slot
            float2 g10 = sg[s][3][2], g11 = sg[s][3][3];
            #pragma unroll
            for (int c = 0; c < 4; c++) {
                float2 n0 = cadd(cmul(g00, r0[c]), cmul(g01, r1[c]));
                float2 n1 = cadd(cmul(g10, r0[c]), cmul(g11, r1[c]));
                r0[c] = n0; r1[c] = n1;
            }
        }
        // ---- Phase D: gather = inverse rotation o CNOT perm ----
        #pragma unroll
        for (int c = 0; c < 4; c++) { sbuf[c][wr0] = r0[c]; sbuf[c][wr1] = r1[c]; }
        __syncthreads();
        if (s == 0) {
            #pragma unroll
            for (int c = 0; c < 4; c++) { r0[c] = sbuf[c][rdD0]; r1[c] = sbuf[c][rdD1]; }
            __syncthreads();
        } else {
            // fold in bit-4 projection + bf16 split, coalesced writes
            #pragma unroll
            for (int c = 0; c < 4; c++) {
                float2 v = sbuf[c][rdP];
                __nv_bfloat16 hr  = __float2bfloat16(v.x);
                __nv_bfloat16 hi2 = __float2bfloat16(v.y);
                size_t base = (size_t)(col0 + c) * DIM;
                g_Gh[base + t]       = hr;
                g_Gh[base + 512 + t] = hi2;
                g_Gl[base + t]       = __float2bfloat16(v.x - __bfloat162float(hr));
                g_Gl[base + 512 + t] = __float2bfloat16(v.y - __bfloat162float(hi2));
            }
        }
    }
}

// ---------------------------------------------------------------------------
// Gram-trace GEMM + fused epilogue + fused final reduction.
//   result = Tr(x) - sum M o y,  M ~= Gh^T Gh + Gh^T Gl + Gl^T Gh
//   bid <  256 : cross (kb,jb) full grid,  A=Gh, B=Gl, wgt -2
//   bid >= 256 : Gram kb<=jb triangle,     A=B=Gh,  wgt -2 (-1 on diagonal)
// Tile 64x64, K=1024, BK=64, NST=16. 256 threads = 8 warps (2x2 warp grid
// x2 warp split-K). 4-slot cp.async ring, 3 stages in flight, ONE barrier
// per stage.
// ---------------------------------------------------------------------------
#define BK    64
#define ROWP  144                 // 128B data + 16B pad
#define OPB   (64 * ROWP)         // 9216
#define STAGE (2 * OPB)           // 18432
#define NST   16                  // K = 1024 / 64
#define NCTA  392
#define GEMM_SMEM (4 * STAGE)     // 73728

__device__ __forceinline__ void issue_stage(uint32_t sb, int c, int tid,
                                            const __nv_bfloat16* Ab, int am0,
                                            const __nv_bfloat16* Bb, int bn0) {
    uint32_t st = sb + (uint32_t)(c & 3) * STAGE;
    int i0 = c * BK;
    #pragma unroll
    for (int r = 0; r < 4; r++) {
        int chunk = r * 256 + tid;            // 1024 chunks of 16B
        int op  = chunk >> 9;                 // 0=A, 1=B
        int c2  = chunk & 511;
        int row = c2 >> 3, seg = c2 & 7;
        uint32_t dst = st + op * OPB + row * ROWP + seg * 16;
        const __nv_bfloat16* base = op ? (Bb + (size_t)(bn0 + row) * DIM)
                                       : (Ab + (size_t)(am0 + row) * DIM);
        CP_ASYNC16(dst, base + i0 + seg * 8);
    }
    CP_COMMIT();
}

__global__ __launch_bounds__(256) void gemm_kernel(const float* __restrict__ x,
                                                   float* __restrict__ out) {
    extern __shared__ char smem[];
    __shared__ float ws[8];
    __shared__ int isLast;
    const uint32_t sb = smem_to_u32(smem);
    int tid = threadIdx.x;
    int w = tid >> 5, lane = tid & 31;
    int bid = blockIdx.x;

    int kb, jb;
    const __nv_bfloat16* Bb;
    float wgt;
    if (bid < 256) {                      // cross term Gh^T Gl, full grid
        kb = bid >> 4; jb = bid & 15;
        Bb = g_Gl; wgt = -2.0f;
    } else {                              // Gram term Gh^T Gh, upper triangle
        int u = bid - 256, rem = 16;
        kb = 0;
        while (u >= rem) { u -= rem; kb++; rem--; }
        jb = kb + u;
        Bb = g_Gh; wgt = (kb == jb) ? -1.0f : -2.0f;
    }
    int am0 = kb * 64, bn0 = jb * 64;

    float acc[2][4][4];
    #pragma unroll
    for (int a = 0; a < 2; a++)
        #pragma unroll
        for (int b = 0; b < 4; b++)
            #pragma unroll
            for (int d = 0; d < 4; d++) acc[a][b][d] = 0.f;

    int wm  = (w & 1) * 32;
    int wn  = ((w >> 1) & 1) * 32;
    int ks0 = (w >> 2) * 2;               // this warp's k16 steps in stage
    int arow = wm + ((lane >> 3) & 1) * 8 + (lane & 7);
    int akb  = (lane >> 4) * 16;
    int brow = wn + (lane >> 4) * 8 + (lane & 7);
    int bkb  = ((lane >> 3) & 1) * 16;

    issue_stage(sb, 0, tid, g_Gh, am0, Bb, bn0);
    issue_stage(sb, 1, tid, g_Gh, am0, Bb, bn0);
    issue_stage(sb, 2, tid, g_Gh, am0, Bb, bn0);

    for (int c = 0; c < NST; c++) {
        if (c < NST - 2)      CP_WAIT2();
        else if (c == NST - 2) CP_WAIT1();
        else                   CP_WAIT0();
        __syncthreads();                  // stage c visible; slot (c+3)&3 free
        if (c + 3 < NST)
            issue_stage(sb, c + 3, tid, g_Gh, am0, Bb, bn0);

        uint32_t st = sb + (uint32_t)(c & 3) * STAGE;
        #pragma unroll
        for (int kss = 0; kss < 2; kss++) {
            int ks = ks0 + kss;
            uint32_t aa[2][4], bb[4][2];
            #pragma unroll
            for (int mt = 0; mt < 2; mt++)
                LDSM_X4(aa[mt], st + (arow + mt * 16) * ROWP + ks * 32 + akb);
            #pragma unroll
            for (int np = 0; np < 2; np++) {
                uint32_t r4[4];
                LDSM_X4(r4, st + OPB + (brow + np * 16) * ROWP + ks * 32 + bkb);
                bb[np * 2][0] = r4[0]; bb[np * 2][1] = r4[1];
                bb[np * 2 + 1][0] = r4[2]; bb[np * 2 + 1][1] = r4[3];
            }
            #pragma unroll
            for (int mt = 0; mt < 2; mt++)
                #pragma unroll
                for (int nt = 0; nt < 4; nt++)
                    MMA_BF16(acc[mt][nt], aa[mt], bb[nt]);
        }
    }

    // Epilogue: part = wgt * sum tile[m][n] * y[kg][jg]  (per-warp partial-K
    // accumulators are valid by linearity of the trace)
    int qr = lane >> 2, qc2 = (lane & 3) * 2;
    float part = 0.f;
    #pragma unroll
    for (int mt = 0; mt < 2; mt++) {
        int kg = am0 + wm + mt * 16 + qr;
        #pragma unroll
        for (int nt = 0; nt < 4; nt++) {
            int jg = bn0 + wn + nt * 8 + qc2;
            float2 y0 = *(const float2*)&g_y[kg * DIM + jg];
            float2 y1 = *(const float2*)&g_y[(kg + 8) * DIM + jg];
            part += y0.x * acc[mt][nt][0] + y0.y * acc[mt][nt][1]
                  + y1.x * acc[mt][nt][2] + y1.y * acc[mt][nt][3];
        }
    }
    part *= wgt;

    #pragma unroll
    for (int o = 16; o > 0; o >>= 1)
        part += __shfl_xor_sync(0xffffffffu, part, o);
    if (lane == 0) ws[w] = part;
    __syncthreads();
    if (tid == 0) {
        float tot = 0.f;
        #pragma unroll
        for (int k = 0; k < 8; k++) tot += ws[k];
        g_partials[bid] = tot;
        __threadfence();
        unsigned old = atomicAdd(&g_cnt, 1u);
        isLast = (old == NCTA - 1) ? 1 : 0;
    }
    __syncthreads();

    if (isLast) {
        float v = 0.f;
        for (int i = tid; i < NCTA; i += 256) v += __ldcg(&g_partials[i]);
        for (int i = tid; i < DIM; i += 256) v += x[i * DIM + i];   // + Tr(x)
        #pragma unroll
        for (int o = 16; o > 0; o >>= 1)
            v += __shfl_xor_sync(0xffffffffu, v, o);
        if (lane == 0) ws[w] = v;
        __syncthreads();
        if (tid == 0) {
            float tot = 0.f;
            #pragma unroll
            for (int k = 0; k < 8; k++) tot += ws[k];
            out[0] = tot;
            g_cnt = 0;                     // reset for next graph replay
        }
    }
}

extern "C" void kernel_launch(void* const* d_in, const int* in_sizes, int n_in,
                              void* d_out, int out_size) {
    const float* x = (const float*)d_in[0];      // 1024x1024 row-major
    const float* w = (const float*)d_in[1];      // 30 weights
    cudaFuncSetAttribute(gemm_kernel, cudaFuncAttributeMaxDynamicSharedMemorySize, GEMM_SMEM);
    build_kernel<<<512, 512>>>(w, x);            // 256 circuit blocks + 256 y-tiles
    gemm_kernel<<<NCTA, 256, GEMM_SMEM>>>(x, (float*)d_out);
}

// round 16
// speedup vs baseline: 1.1950x; 1.1950x over previous
#include <cuda_runtime.h>
#include <cuda_bf16.h>
#include <cstdint>

#define DIM 1024

// G = [Re(PE); Im(PE)] (1024 x 1024), stored column-of-G, i-contiguous:
//   g_Gh[m][i] = bf16hi(G[i][m]),  g_Gl[m][i] = bf16lo
__device__ __nv_bfloat16 g_Gh[DIM * DIM];
__device__ __nv_bfloat16 g_Gl[DIM * DIM];
__device__ float         g_y [DIM * DIM];      // y = x + x^T
__device__ float         g_partials[392];
__device__ unsigned      g_cnt;                // zero-init; reset by last CTA

__device__ __forceinline__ uint32_t smem_to_u32(const void* p) {
    uint32_t a;
    asm("{ .reg .u64 t; cvta.to.shared.u64 t, %1; cvt.u32.u64 %0, t; }" : "=r"(a) : "l"(p));
    return a;
}

#define CP_ASYNC16(dst, src) \
    asm volatile("cp.async.ca.shared.global [%0], [%1], 16;" :: "r"(dst), "l"(src) : "memory")
#define CP_COMMIT() asm volatile("cp.async.commit_group;" ::: "memory")
#define CP_WAIT2()  asm volatile("cp.async.wait_group 2;" ::: "memory")
#define CP_WAIT1()  asm volatile("cp.async.wait_group 1;" ::: "memory")
#define CP_WAIT0()  asm volatile("cp.async.wait_group 0;" ::: "memory")

#define LDSM_X4(r, a) \
    asm volatile("ldmatrix.sync.aligned.m8n8.x4.shared.b16 {%0,%1,%2,%3}, [%4];" \
        : "=r"((r)[0]), "=r"((r)[1]), "=r"((r)[2]), "=r"((r)[3]) : "r"(a))

#define MMA_BF16(d, a, b) \
    asm volatile("mma.sync.aligned.m16n8k16.row.col.f32.bf16.bf16.f32 " \
        "{%0,%1,%2,%3},{%4,%5,%6,%7},{%8,%9},{%0,%1,%2,%3};" \
        : "+f"((d)[0]), "+f"((d)[1]), "+f"((d)[2]), "+f"((d)[3]) \
        : "r"((a)[0]), "r"((a)[1]), "r"((a)[2]), "r"((a)[3]), \
          "r"((b)[0]), "r"((b)[1]))

__device__ __forceinline__ float2 cmul(float2 a, float2 b) {
    return make_float2(a.x * b.x - a.y * b.y, a.x * b.y + a.y * b.x);
}
__device__ __forceinline__ float2 cadd(float2 a, float2 b) {
    return make_float2(a.x + b.x, a.y + b.y);
}

// ---------------------------------------------------------------------------
// Build kernel (R14 version — best measured): register-resident statevector,
// 4 columns per block.
//   blocks [0,256): simulate basis columns 4b..4b+3. Thread t holds states
//     {2t, 2t+1} per column in registers. Gates on state-bit p:
//       p=0: thread-local pair; p in [1,5]: shfl.xor lane exchange;
//       p in [6,9]: smem exchange. CNOT chain = one smem permutation gather.
//   blocks [256,512): 64x64 tiles of y = x + x^T.
// ---------------------------------------------------------------------------
__global__ __launch_bounds__(512) void build_kernel(const float* __restrict__ w,
                                                    const float* __restrict__ x) {
    __shared__ float2 sg[2][10][4];
    __shared__ __align__(16) char sraw[32768];
    int t = threadIdx.x;

    if (blockIdx.x >= 256) {
        // ---- y = x + x^T, 64x64 tile ----
        float (*tl)[65] = (float (*)[65])sraw;     // 64*65*4 = 16640 B
        int id = blockIdx.x - 256;                 // 0..255
        int a0c = (id >> 4) * 64, b0c = (id & 15) * 64;
        int tx = t & 63, ty = t >> 6;              // 64 x 8
        #pragma unroll
        for (int r = 0; r < 8; r++)                // tl[c][rr] = x[b0+rr][a0+c]
            tl[tx][ty + 8 * r] = x[(b0c + ty + 8 * r) * DIM + a0c + tx];
        __syncthreads();
        #pragma unroll
        for (int r = 0; r < 8; r++) {
            int a = a0c + ty + 8 * r;
            g_y[a * DIM + b0c + tx] = x[a * DIM + b0c + tx] + tl[ty + 8 * r][tx];
        }
        return;
    }

    if (t < 20) {
        int s = t / 10, q = t % 10;
        float sign = s ? -1.f : 1.f;
        const float WM = 0.63245553203367586f;  // sqrt(2/5)
        float hx = 0.5f * sign * w[q]      * WM;
        float hy = 0.5f * sign * w[q + 10] * WM;
        float hz = 0.5f * sign * w[q + 20] * WM;
        float cx, sx, cy, sy, cz, sz;
        sincosf(hx, &sx, &cx);
        sincosf(hy, &sy, &cy);
        sincosf(hz, &sz, &cz);
        float2 T00 = make_float2( cy * cx,  sy * sx);
        float2 T01 = make_float2(-sy * cx, -cy * sx);
        float2 T10 = make_float2( sy * cx, -cy * sx);
        float2 T11 = make_float2( cy * cx, -sy * sx);
        float2 e0 = make_float2(cz, -sz);
        float2 e1 = make_float2(cz,  sz);
        sg[s][q][0] = cmul(e0, T00);
        sg[s][q][1] = cmul(e0, T01);
        sg[s][q][2] = cmul(e1, T10);
        sg[s][q][3] = cmul(e1, T11);
    }

    int col0 = blockIdx.x * 4;
    float2 a0[4], a1[4];
    #pragma unroll
    for (int c = 0; c < 4; c++) {
        int col = col0 + c;
        a0[c] = make_float2((2 * t == col)     ? 1.f : 0.f, 0.f);
        a1[c] = make_float2((2 * t + 1 == col) ? 1.f : 0.f, 0.f);
    }
    __syncthreads();                               // sg visible

    float4 (*bufx)[512]  = (float4 (*)[512])sraw;  // [4][512]  = 32 KB
    float2 (*buf2)[1024] = (float2 (*)[1024])sraw; // [4][1024] = 32 KB

    // Permutation target indices (loop-invariant)
    int j0 = 2 * t, j1 = 2 * t + 1;
    #pragma unroll
    for (int q = 9; q >= 1; q--) {
        int pc = 10 - q, pt = 9 - q;
        if ((j0 >> pc) & 1) j0 ^= (1 << pt);
        if ((j1 >> pc) & 1) j1 ^= (1 << pt);
    }

    for (int s = 0; s < 2; s++) {
        // ---- gates on bits p = 9..6 : smem exchange ----
        #pragma unroll
        for (int p = 9; p >= 6; p--) {
            float2 g00 = sg[s][9 - p][0], g01 = sg[s][9 - p][1];
            float2 g10 = sg[s][9 - p][2], g11 = sg[s][9 - p][3];
            int tp = t ^ (1 << (p - 1));
            int b  = (t >> (p - 1)) & 1;
            #pragma unroll
            for (int c = 0; c < 4; c++)
                bufx[c][t] = make_float4(a0[c].x, a0[c].y, a1[c].x, a1[c].y);
            __syncthreads();
            #pragma unroll
            for (int c = 0; c < 4; c++) {
                float4 o = bufx[c][tp];
                float2 o0 = make_float2(o.x, o.y), o1 = make_float2(o.z, o.w);
                if (b == 0) {
                    a0[c] = cadd(cmul(g00, a0[c]), cmul(g01, o0));
                    a1[c] = cadd(cmul(g00, a1[c]), cmul(g01, o1));
                } else {
                    a0[c] = cadd(cmul(g10, o0), cmul(g11, a0[c]));
                    a1[c] = cadd(cmul(g10, o1), cmul(g11, a1[c]));
                }
            }
            __syncthreads();
        }
        // ---- gates on bits p = 5..1 : shfl exchange ----
        #pragma unroll
        for (int p = 5; p >= 1; p--) {
            float2 g00 = sg[s][9 - p][0], g01 = sg[s][9 - p][1];
            float2 g10 = sg[s][9 - p][2], g11 = sg[s][9 - p][3];
            int m = 1 << (p - 1);
            int b = (t >> (p - 1)) & 1;
            #pragma unroll
            for (int c = 0; c < 4; c++) {
                float2 o0, o1;
                o0.x = __shfl_xor_sync(0xffffffffu, a0[c].x, m);
                o0.y = __shfl_xor_sync(0xffffffffu, a0[c].y, m);
                o1.x = __shfl_xor_sync(0xffffffffu, a1[c].x, m);
                o1.y = __shfl_xor_sync(0xffffffffu, a1[c].y, m);
                if (b == 0) {
                    a0[c] = cadd(cmul(g00, a0[c]), cmul(g01, o0));
                    a1[c] = cadd(cmul(g00, a1[c]), cmul(g01, o1));
                } else {
                    a0[c] = cadd(cmul(g10, o0), cmul(g11, a0[c]));
                    a1[c] = cadd(cmul(g10, o1), cmul(g11, a1[c]));
                }
            }
        }
        // ---- gate on bit 0 : thread-local ----
        {
            float2 g00 = sg[s][9][0], g01 = sg[s][9][1];
            float2 g10 = sg[s][9][2], g11 = sg[s][9][3];
            #pragma unroll
            for (int c = 0; c < 4; c++) {
                float2 n0 = cadd(cmul(g00, a0[c]), cmul(g01, a1[c]));
                float2 n1 = cadd(cmul(g10, a0[c]), cmul(g11, a1[c]));
                a0[c] = n0; a1[c] = n1;
            }
        }
        // ---- CNOT chain as one permutation gather ----
        #pragma unroll
        for (int c = 0; c < 4; c++) {
            buf2[c][2 * t]     = a0[c];
            buf2[c][2 * t + 1] = a1[c];
        }
        __syncthreads();
        #pragma unroll
        for (int c = 0; c < 4; c++) {
            a0[c] = buf2[c][j0];
            a1[c] = buf2[c][j1];
        }
        __syncthreads();
    }

    // Projection onto bit4-set states + bf16 split, coalesced writes.
    #pragma unroll
    for (int c = 0; c < 4; c++) {
        buf2[c][2 * t]     = a0[c];
        buf2[c][2 * t + 1] = a1[c];
    }
    __syncthreads();
    int st = ((t & ~15) << 1) | 16 | (t & 15);     // insert 1 at bit 4
    #pragma unroll
    for (int c = 0; c < 4; c++) {
        float2 v = buf2[c][st];
        __nv_bfloat16 hr  = __float2bfloat16(v.x);
        __nv_bfloat16 hi2 = __float2bfloat16(v.y);
        size_t base = (size_t)(col0 + c) * DIM;
        g_Gh[base + t]       = hr;
        g_Gh[base + 512 + t] = hi2;
        g_Gl[base + t]       = __float2bfloat16(v.x - __bfloat162float(hr));
        g_Gl[base + 512 + t] = __float2bfloat16(v.y - __bfloat162float(hi2));
    }
}

// ---------------------------------------------------------------------------
// Gram-trace GEMM + fused epilogue + fused final reduction (R15 version).
//   result = Tr(x) - sum M o y,  M ~= Gh^T Gh + Gh^T Gl + Gl^T Gh
//   bid <  256 : cross (kb,jb) full grid,  A=Gh, B=Gl, wgt -2
//   bid >= 256 : Gram kb<=jb triangle,     A=B=Gh,  wgt -2 (-1 on diagonal)
// Tile 64x64, K=1024, BK=64, NST=16. 256 threads = 8 warps (2x2 warp grid
// x2 warp split-K). 4-slot cp.async ring, 3 stages in flight, ONE barrier
// per stage.
// ---------------------------------------------------------------------------
#define BK    64
#define ROWP  144                 // 128B data + 16B pad
#define OPB   (64 * ROWP)         // 9216
#define STAGE (2 * OPB)           // 18432
#define NST   16                  // K = 1024 / 64
#define NCTA  392
#define GEMM_SMEM (4 * STAGE)     // 73728

__device__ __forceinline__ void issue_stage(uint32_t sb, int c, int tid,
                                            const __nv_bfloat16* Ab, int am0,
                                            const __nv_bfloat16* Bb, int bn0) {
    uint32_t st = sb + (uint32_t)(c & 3) * STAGE;
    int i0 = c * BK;
    #pragma unroll
    for (int r = 0; r < 4; r++) {
        int chunk = r * 256 + tid;            // 1024 chunks of 16B
        int op  = chunk >> 9;                 // 0=A, 1=B
        int c2  = chunk & 511;
        int row = c2 >> 3, seg = c2 & 7;
        uint32_t dst = st + op * OPB + row * ROWP + seg * 16;
        const __nv_bfloat16* base = op ? (Bb + (size_t)(bn0 + row) * DIM)
                                       : (Ab + (size_t)(am0 + row) * DIM);
        CP_ASYNC16(dst, base + i0 + seg * 8);
    }
    CP_COMMIT();
}

__global__ __launch_bounds__(256) void gemm_kernel(const float* __restrict__ x,
                                                   float* __restrict__ out) {
    extern __shared__ char smem[];
    __shared__ float ws[8];
    __shared__ int isLast;
    const uint32_t sb = smem_to_u32(smem);
    int tid = threadIdx.x;
    int w = tid >> 5, lane = tid & 31;
    int bid = blockIdx.x;

    int kb, jb;
    const __nv_bfloat16* Bb;
    float wgt;
    if (bid < 256) {                      // cross term Gh^T Gl, full grid
        kb = bid >> 4; jb = bid & 15;
        Bb = g_Gl; wgt = -2.0f;
    } else {                              // Gram term Gh^T Gh, upper triangle
        int u = bid - 256, rem = 16;
        kb = 0;
        while (u >= rem) { u -= rem; kb++; rem--; }
        jb = kb + u;
        Bb = g_Gh; wgt = (kb == jb) ? -1.0f : -2.0f;
    }
    int am0 = kb * 64, bn0 = jb * 64;

    float acc[2][4][4];
    #pragma unroll
    for (int a = 0; a < 2; a++)
        #pragma unroll
        for (int b = 0; b < 4; b++)
            #pragma unroll
            for (int d = 0; d < 4; d++) acc[a][b][d] = 0.f;

    int wm  = (w & 1) * 32;
    int wn  = ((w >> 1) & 1) * 32;
    int ks0 = (w >> 2) * 2;               // this warp's k16 steps in stage
    int arow = wm + ((lane >> 3) & 1) * 8 + (lane & 7);
    int akb  = (lane >> 4) * 16;
    int brow = wn + (lane >> 4) * 8 + (lane & 7);
    int bkb  = ((lane >> 3) & 1) * 16;

    issue_stage(sb, 0, tid, g_Gh, am0, Bb, bn0);
    issue_stage(sb, 1, tid, g_Gh, am0, Bb, bn0);
    issue_stage(sb, 2, tid, g_Gh, am0, Bb, bn0);

    for (int c = 0; c < NST; c++) {
        if (c < NST - 2)       CP_WAIT2();
        else if (c == NST - 2) CP_WAIT1();
        else                   CP_WAIT0();
        __syncthreads();                  // stage c visible; slot (c+3)&3 free
        if (c + 3 < NST)
            issue_stage(sb, c + 3, tid, g_Gh, am0, Bb, bn0);

        uint32_t st = sb + (uint32_t)(c & 3) * STAGE;
        #pragma unroll
        for (int kss = 0; kss < 2; kss++) {
            int ks = ks0 + kss;
            uint32_t aa[2][4], bb[4][2];
            #pragma unroll
            for (int mt = 0; mt < 2; mt++)
                LDSM_X4(aa[mt], st + (arow + mt * 16) * ROWP + ks * 32 + akb);
            #pragma unroll
            for (int np = 0; np < 2; np++) {
                uint32_t r4[4];
                LDSM_X4(r4, st + OPB + (brow + np * 16) * ROWP + ks * 32 + bkb);
                bb[np * 2][0] = r4[0]; bb[np * 2][1] = r4[1];
                bb[np * 2 + 1][0] = r4[2]; bb[np * 2 + 1][1] = r4[3];
            }
            #pragma unroll
            for (int mt = 0; mt < 2; mt++)
                #pragma unroll
                for (int nt = 0; nt < 4; nt++)
                    MMA_BF16(acc[mt][nt], aa[mt], bb[nt]);
        }
    }

    // Epilogue: part = wgt * sum tile[m][n] * y[kg][jg]  (per-warp partial-K
    // accumulators are valid by linearity of the trace)
    int qr = lane >> 2, qc2 = (lane & 3) * 2;
    float part = 0.f;
    #pragma unroll
    for (int mt = 0; mt < 2; mt++) {
        int kg = am0 + wm + mt * 16 + qr;
        #pragma unroll
        for (int nt = 0; nt < 4; nt++) {
            int jg = bn0 + wn + nt * 8 + qc2;
            float2 y0 = *(const float2*)&g_y[kg * DIM + jg];
            float2 y1 = *(const float2*)&g_y[(kg + 8) * DIM + jg];
            part += y0.x * acc[mt][nt][0] + y0.y * acc[mt][nt][1]
                  + y1.x * acc[mt][nt][2] + y1.y * acc[mt][nt][3];
        }
    }
    part *= wgt;

    #pragma unroll
    for (int o = 16; o > 0; o >>= 1)
        part += __shfl_xor_sync(0xffffffffu, part, o);
    if (lane == 0) ws[w] = part;
    __syncthreads();
    if (tid == 0) {
        float tot = 0.f;
        #pragma unroll
        for (int k = 0; k < 8; k++) tot += ws[k];
        g_partials[bid] = tot;
        __threadfence();
        unsigned old = atomicAdd(&g_cnt, 1u);
        isLast = (old == NCTA - 1) ? 1 : 0;
    }
    __syncthreads();

    if (isLast) {
        float v = 0.f;
        for (int i = tid; i < NCTA; i += 256) v += __ldcg(&g_partials[i]);
        for (int i = tid; i < DIM; i += 256) v += x[i * DIM + i];   // + Tr(x)
        #pragma unroll
        for (int o = 16; o > 0; o >>= 1)
            v += __shfl_xor_sync(0xffffffffu, v, o);
        if (lane == 0) ws[w] = v;
        __syncthreads();
        if (tid == 0) {
            float tot = 0.f;
            #pragma unroll
            for (int k = 0; k < 8; k++) tot += ws[k];
            out[0] = tot;
            g_cnt = 0;                     // reset for next graph replay
        }
    }
}

extern "C" void kernel_launch(void* const* d_in, const int* in_sizes, int n_in,
                              void* d_out, int out_size) {
    const float* x = (const float*)d_in[0];      // 1024x1024 row-major
    const float* w = (const float*)d_in[1];      // 30 weights
    cudaFuncSetAttribute(gemm_kernel, cudaFuncAttributeMaxDynamicSharedMemorySize, GEMM_SMEM);
    build_kernel<<<512, 512>>>(w, x);            // 256 circuit blocks + 256 y-tiles
    gemm_kernel<<<NCTA, 256, GEMM_SMEM>>>(x, (float*)d_out);
}

// round 17
// speedup vs baseline: 1.3097x; 1.0960x over previous
#include <cuda_runtime.h>
#include <cuda_bf16.h>
#include <cstdint>

#define DIM 1024

// G = [Re(PE); Im(PE)] (1024 x 1024), stored column-of-G, i-contiguous:
//   g_Gh[m][i] = bf16hi(G[i][m]),  g_Gl[m][i] = bf16lo
__device__ __nv_bfloat16 g_Gh[DIM * DIM];
__device__ __nv_bfloat16 g_Gl[DIM * DIM];
__device__ float         g_y [DIM * DIM];      // y = x + x^T
__device__ float         g_partials[392];
__device__ unsigned      g_cnt;                // zero-init; reset by last CTA

__device__ __forceinline__ uint32_t smem_to_u32(const void* p) {
    uint32_t a;
    asm("{ .reg .u64 t; cvta.to.shared.u64 t, %1; cvt.u32.u64 %0, t; }" : "=r"(a) : "l"(p));
    return a;
}

#define CP_ASYNC16(dst, src) \
    asm volatile("cp.async.ca.shared.global [%0], [%1], 16;" :: "r"(dst), "l"(src) : "memory")
#define CP_COMMIT() asm volatile("cp.async.commit_group;" ::: "memory")
#define CP_WAIT2()  asm volatile("cp.async.wait_group 2;" ::: "memory")
#define CP_WAIT1()  asm volatile("cp.async.wait_group 1;" ::: "memory")
#define CP_WAIT0()  asm volatile("cp.async.wait_group 0;" ::: "memory")

#define LDSM_X4(r, a) \
    asm volatile("ldmatrix.sync.aligned.m8n8.x4.shared.b16 {%0,%1,%2,%3}, [%4];" \
        : "=r"((r)[0]), "=r"((r)[1]), "=r"((r)[2]), "=r"((r)[3]) : "r"(a))

#define MMA_BF16(d, a, b) \
    asm volatile("mma.sync.aligned.m16n8k16.row.col.f32.bf16.bf16.f32 " \
        "{%0,%1,%2,%3},{%4,%5,%6,%7},{%8,%9},{%0,%1,%2,%3};" \
        : "+f"((d)[0]), "+f"((d)[1]), "+f"((d)[2]), "+f"((d)[3]) \
        : "r"((a)[0]), "r"((a)[1]), "r"((a)[2]), "r"((a)[3]), \
          "r"((b)[0]), "r"((b)[1]))

__device__ __forceinline__ float2 cmul(float2 a, float2 b) {
    return make_float2(a.x * b.x - a.y * b.y, a.x * b.y + a.y * b.x);
}
__device__ __forceinline__ float2 cadd(float2 a, float2 b) {
    return make_float2(a.x + b.x, a.y + b.y);
}

// CNOT chain q=1..9 source index for output state s.
__device__ __forceinline__ int cnot_src(int s) {
    int j = s;
    #pragma unroll
    for (int q = 9; q >= 1; q--) {
        int pc = 10 - q, pt = 9 - q;
        if ((j >> pc) & 1) j ^= (1 << pt);
    }
    return j;
}

// ---------------------------------------------------------------------------
// Build kernel. Pass 1 (sign +) applied to a BASIS state is a tensor-product
// state, so (gates + CNOT chain) collapse to a closed-form 10-factor complex
// product per amplitude — no exchanges, no barriers. Pass 2 (dense input)
// uses the validated exchange machinery: smem XOR-exchange for state bits
// 9..6, shfl for 5..1, local for 0; its CNOT gather is merged with the final
// bit-4 projection gather (single smem round-trip).
//   blocks [0,256): circuit, 4 columns per block, thread t holds {2t, 2t+1}.
//   blocks [256,512): 64x64 tiles of y = x + x^T.
// ---------------------------------------------------------------------------
__global__ __launch_bounds__(512) void build_kernel(const float* __restrict__ w,
                                                    const float* __restrict__ x) {
    __shared__ float2 sg[2][10][4];
    __shared__ __align__(16) char sraw[32768];
    int t = threadIdx.x;

    if (blockIdx.x >= 256) {
        // ---- y = x + x^T, 64x64 tile ----
        float (*tl)[65] = (float (*)[65])sraw;     // 64*65*4 = 16640 B
        int id = blockIdx.x - 256;                 // 0..255
        int a0c = (id >> 4) * 64, b0c = (id & 15) * 64;
        int tx = t & 63, ty = t >> 6;              // 64 x 8
        #pragma unroll
        for (int r = 0; r < 8; r++)                // tl[c][rr] = x[b0+rr][a0+c]
            tl[tx][ty + 8 * r] = x[(b0c + ty + 8 * r) * DIM + a0c + tx];
        __syncthreads();
        #pragma unroll
        for (int r = 0; r < 8; r++) {
            int a = a0c + ty + 8 * r;
            g_y[a * DIM + b0c + tx] = x[a * DIM + b0c + tx] + tl[ty + 8 * r][tx];
        }
        return;
    }

    if (t < 20) {
        int s = t / 10, q = t % 10;
        float sign = s ? -1.f : 1.f;
        const float WM = 0.63245553203367586f;  // sqrt(2/5)
        float hx = 0.5f * sign * w[q]      * WM;
        float hy = 0.5f * sign * w[q + 10] * WM;
        float hz = 0.5f * sign * w[q + 20] * WM;
        float cx, sx, cy, sy, cz, sz;
        sincosf(hx, &sx, &cx);
        sincosf(hy, &sy, &cy);
        sincosf(hz, &sz, &cz);
        float2 T00 = make_float2( cy * cx,  sy * sx);
        float2 T01 = make_float2(-sy * cx, -cy * sx);
        float2 T10 = make_float2( sy * cx, -cy * sx);
        float2 T11 = make_float2( cy * cx, -sy * sx);
        float2 e0 = make_float2(cz, -sz);
        float2 e1 = make_float2(cz,  sz);
        sg[s][q][0] = cmul(e0, T00);
        sg[s][q][1] = cmul(e0, T01);
        sg[s][q][2] = cmul(e1, T10);
        sg[s][q][3] = cmul(e1, T11);
    }

    int col0 = blockIdx.x * 4;
    float4 (*bufx)[512]  = (float4 (*)[512])sraw;  // [4][512]  = 32 KB
    float2 (*buf2)[1024] = (float2 (*)[1024])sraw; // [4][1024] = 32 KB

    // Loop-invariant indices
    int j0 = cnot_src(2 * t), j1 = cnot_src(2 * t + 1);
    int stp = ((t & ~15) << 1) | 16 | (t & 15);    // projected state (bit4=1)
    int rdF = cnot_src(stp);                       // pass-2 perm + projection

    __syncthreads();                               // sg visible

    // ---- Pass 1 (sign +): closed form.  amp(s) = prod_q G_q[bit_{9-q}(j)]
    //      [bit_{9-q}(col)], j = cnot_src(s). Cols share bits 9..2 -> shared
    //      8-factor prefix; bits 1..0 give per-col tail factors. ----
    float2 a0[4], a1[4];
    {
        float2 pre0 = sg[0][0][((j0 >> 9) & 1) * 2 + ((col0 >> 9) & 1)];
        float2 pre1 = sg[0][0][((j1 >> 9) & 1) * 2 + ((col0 >> 9) & 1)];
        #pragma unroll
        for (int q = 1; q < 8; q++) {
            int p = 9 - q;
            int cb = (col0 >> p) & 1;
            pre0 = cmul(pre0, sg[0][q][((j0 >> p) & 1) * 2 + cb]);
            pre1 = cmul(pre1, sg[0][q][((j1 >> p) & 1) * 2 + cb]);
        }
        int b8_0 = ((j0 >> 1) & 1) * 2, b9_0 = (j0 & 1) * 2;
        int b8_1 = ((j1 >> 1) & 1) * 2, b9_1 = (j1 & 1) * 2;
        #pragma unroll
        for (int c = 0; c < 4; c++) {
            a0[c] = cmul(cmul(pre0, sg[0][8][b8_0 + (c >> 1)]), sg[0][9][b9_0 + (c & 1)]);
            a1[c] = cmul(cmul(pre1, sg[0][8][b8_1 + (c >> 1)]), sg[0][9][b9_1 + (c & 1)]);
        }
    }

    // ---- Pass 2 (sign -): dense. smem exchange bits 9..6 ----
    #pragma unroll
    for (int p = 9; p >= 6; p--) {
        float2 g00 = sg[1][9 - p][0], g01 = sg[1][9 - p][1];
        float2 g10 = sg[1][9 - p][2], g11 = sg[1][9 - p][3];
        int tp = t ^ (1 << (p - 1));
        int b  = (t >> (p - 1)) & 1;
        #pragma unroll
        for (int c = 0; c < 4; c++)
            bufx[c][t] = make_float4(a0[c].x, a0[c].y, a1[c].x, a1[c].y);
        __syncthreads();
        #pragma unroll
        for (int c = 0; c < 4; c++) {
            float4 o = bufx[c][tp];
            float2 o0 = make_float2(o.x, o.y), o1 = make_float2(o.z, o.w);
            if (b == 0) {
                a0[c] = cadd(cmul(g00, a0[c]), cmul(g01, o0));
                a1[c] = cadd(cmul(g00, a1[c]), cmul(g01, o1));
            } else {
                a0[c] = cadd(cmul(g10, o0), cmul(g11, a0[c]));
                a1[c] = cadd(cmul(g10, o1), cmul(g11, a1[c]));
            }
        }
        __syncthreads();
    }
    // ---- shfl exchange bits 5..1 ----
    #pragma unroll
    for (int p = 5; p >= 1; p--) {
        float2 g00 = sg[1][9 - p][0], g01 = sg[1][9 - p][1];
        float2 g10 = sg[1][9 - p][2], g11 = sg[1][9 - p][3];
        int m = 1 << (p - 1);
        int b = (t >> (p - 1)) & 1;
        #pragma unroll
        for (int c = 0; c < 4; c++) {
            float2 o0, o1;
            o0.x = __shfl_xor_sync(0xffffffffu, a0[c].x, m);
            o0.y = __shfl_xor_sync(0xffffffffu, a0[c].y, m);
            o1.x = __shfl_xor_sync(0xffffffffu, a1[c].x, m);
            o1.y = __shfl_xor_sync(0xffffffffu, a1[c].y, m);
            if (b == 0) {
                a0[c] = cadd(cmul(g00, a0[c]), cmul(g01, o0));
                a1[c] = cadd(cmul(g00, a1[c]), cmul(g01, o1));
            } else {
                a0[c] = cadd(cmul(g10, o0), cmul(g11, a0[c]));
                a1[c] = cadd(cmul(g10, o1), cmul(g11, a1[c]));
            }
        }
    }
    // ---- local bit 0 ----
    {
        float2 g00 = sg[1][9][0], g01 = sg[1][9][1];
        float2 g10 = sg[1][9][2], g11 = sg[1][9][3];
        #pragma unroll
        for (int c = 0; c < 4; c++) {
            float2 n0 = cadd(cmul(g00, a0[c]), cmul(g01, a1[c]));
            float2 n1 = cadd(cmul(g10, a0[c]), cmul(g11, a1[c]));
            a0[c] = n0; a1[c] = n1;
        }
    }
    // ---- final gather: CNOT perm o bit-4 projection, + bf16 split ----
    #pragma unroll
    for (int c = 0; c < 4; c++) {
        buf2[c][2 * t]     = a0[c];
        buf2[c][2 * t + 1] = a1[c];
    }
    __syncthreads();
    #pragma unroll
    for (int c = 0; c < 4; c++) {
        float2 v = buf2[c][rdF];
        __nv_bfloat16 hr  = __float2bfloat16(v.x);
        __nv_bfloat16 hi2 = __float2bfloat16(v.y);
        size_t base = (size_t)(col0 + c) * DIM;
        g_Gh[base + t]       = hr;
        g_Gh[base + 512 + t] = hi2;
        g_Gl[base + t]       = __float2bfloat16(v.x - __bfloat162float(hr));
        g_Gl[base + 512 + t] = __float2bfloat16(v.y - __bfloat162float(hi2));
    }
}

// ---------------------------------------------------------------------------
// Gram-trace GEMM + fused epilogue + fused final reduction (R16 version,
// unchanged).
//   result = Tr(x) - sum M o y,  M ~= Gh^T Gh + Gh^T Gl + Gl^T Gh
//   bid <  256 : cross (kb,jb) full grid,  A=Gh, B=Gl, wgt -2
//   bid >= 256 : Gram kb<=jb triangle,     A=B=Gh,  wgt -2 (-1 on diagonal)
// Tile 64x64, K=1024, BK=64, NST=16. 256 threads = 8 warps (2x2 warp grid
// x2 warp split-K). 4-slot cp.async ring, 3 stages in flight, ONE barrier
// per stage.
// ---------------------------------------------------------------------------
#define BK    64
#define ROWP  144                 // 128B data + 16B pad
#define OPB   (64 * ROWP)         // 9216
#define STAGE (2 * OPB)           // 18432
#define NST   16                  // K = 1024 / 64
#define NCTA  392
#define GEMM_SMEM (4 * STAGE)     // 73728

__device__ __forceinline__ void issue_stage(uint32_t sb, int c, int tid,
                                            const __nv_bfloat16* Ab, int am0,
                                            const __nv_bfloat16* Bb, int bn0) {
    uint32_t st = sb + (uint32_t)(c & 3) * STAGE;
    int i0 = c * BK;
    #pragma unroll
    for (int r = 0; r < 4; r++) {
        int chunk = r * 256 + tid;            // 1024 chunks of 16B
        int op  = chunk >> 9;                 // 0=A, 1=B
        int c2  = chunk & 511;
        int row = c2 >> 3, seg = c2 & 7;
        uint32_t dst = st + op * OPB + row * ROWP + seg * 16;
        const __nv_bfloat16* base = op ? (Bb + (size_t)(bn0 + row) * DIM)
                                       : (Ab + (size_t)(am0 + row) * DIM);
        CP_ASYNC16(dst, base + i0 + seg * 8);
    }
    CP_COMMIT();
}

__global__ __launch_bounds__(256) void gemm_kernel(const float* __restrict__ x,
                                                   float* __restrict__ out) {
    extern __shared__ char smem[];
    __shared__ float ws[8];
    __shared__ int isLast;
    const uint32_t sb = smem_to_u32(smem);
    int tid = threadIdx.x;
    int w = tid >> 5, lane = tid & 31;
    int bid = blockIdx.x;

    int kb, jb;
    const __nv_bfloat16* Bb;
    float wgt;
    if (bid < 256) {                      // cross term Gh^T Gl, full grid
        kb = bid >> 4; jb = bid & 15;
        Bb = g_Gl; wgt = -2.0f;
    } else {                              // Gram term Gh^T Gh, upper triangle
        int u = bid - 256, rem = 16;
        kb = 0;
        while (u >= rem) { u -= rem; kb++; rem--; }
        jb = kb + u;
        Bb = g_Gh; wgt = (kb == jb) ? -1.0f : -2.0f;
    }
    int am0 = kb * 64, bn0 = jb * 64;

    float acc[2][4][4];
    #pragma unroll
    for (int a = 0; a < 2; a++)
        #pragma unroll
        for (int b = 0; b < 4; b++)
            #pragma unroll
            for (int d = 0; d < 4; d++) acc[a][b][d] = 0.f;

    int wm  = (w & 1) * 32;
    int wn  = ((w >> 1) & 1) * 32;
    int ks0 = (w >> 2) * 2;               // this warp's k16 steps in stage
    int arow = wm + ((lane >> 3) & 1) * 8 + (lane & 7);
    int akb  = (lane >> 4) * 16;
    int brow = wn + (lane >> 4) * 8 + (lane & 7);
    int bkb  = ((lane >> 3) & 1) * 16;

    issue_stage(sb, 0, tid, g_Gh, am0, Bb, bn0);
    issue_stage(sb, 1, tid, g_Gh, am0, Bb, bn0);
    issue_stage(sb, 2, tid, g_Gh, am0, Bb, bn0);

    for (int c = 0; c < NST; c++) {
        if (c < NST - 2)       CP_WAIT2();
        else if (c == NST - 2) CP_WAIT1();
        else                   CP_WAIT0();
        __syncthreads();                  // stage c visible; slot (c+3)&3 free
        if (c + 3 < NST)
            issue_stage(sb, c + 3, tid, g_Gh, am0, Bb, bn0);

        uint32_t st = sb + (uint32_t)(c & 3) * STAGE;
        #pragma unroll
        for (int kss = 0; kss < 2; kss++) {
            int ks = ks0 + kss;
            uint32_t aa[2][4], bb[4][2];
            #pragma unroll
            for (int mt = 0; mt < 2; mt++)
                LDSM_X4(aa[mt], st + (arow + mt * 16) * ROWP + ks * 32 + akb);
            #pragma unroll
            for (int np = 0; np < 2; np++) {
                uint32_t r4[4];
                LDSM_X4(r4, st + OPB + (brow + np * 16) * ROWP + ks * 32 + bkb);
                bb[np * 2][0] = r4[0]; bb[np * 2][1] = r4[1];
                bb[np * 2 + 1][0] = r4[2]; bb[np * 2 + 1][1] = r4[3];
            }
            #pragma unroll
            for (int mt = 0; mt < 2; mt++)
                #pragma unroll
                for (int nt = 0; nt < 4; nt++)
                    MMA_BF16(acc[mt][nt], aa[mt], bb[nt]);
        }
    }

    // Epilogue: part = wgt * sum tile[m][n] * y[kg][jg]  (per-warp partial-K
    // accumulators are valid by linearity of the trace)
    int qr = lane >> 2, qc2 = (lane & 3) * 2;
    float part = 0.f;
    #pragma unroll
    for (int mt = 0; mt < 2; mt++) {
        int kg = am0 + wm + mt * 16 + qr;
        #pragma unroll
        for (int nt = 0; nt < 4; nt++) {
            int jg = bn0 + wn + nt * 8 + qc2;
            float2 y0 = *(const float2*)&g_y[kg * DIM + jg];
            float2 y1 = *(const float2*)&g_y[(kg + 8) * DIM + jg];
            part += y0.x * acc[mt][nt][0] + y0.y * acc[mt][nt][1]
                  + y1.x * acc[mt][nt][2] + y1.y * acc[mt][nt][3];
        }
    }
    part *= wgt;

    #pragma unroll
    for (int o = 16; o > 0; o >>= 1)
        part += __shfl_xor_sync(0xffffffffu, part, o);
    if (lane == 0) ws[w] = part;
    __syncthreads();
    if (tid == 0) {
        float tot = 0.f;
        #pragma unroll
        for (int k = 0; k < 8; k++) tot += ws[k];
        g_partials[bid] = tot;
        __threadfence();
        unsigned old = atomicAdd(&g_cnt, 1u);
        isLast = (old == NCTA - 1) ? 1 : 0;
    }
    __syncthreads();

    if (isLast) {
        float v = 0.f;
        for (int i = tid; i < NCTA; i += 256) v += __ldcg(&g_partials[i]);
        for (int i = tid; i < DIM; i += 256) v += x[i * DIM + i];   // + Tr(x)
        #pragma unroll
        for (int o = 16; o > 0; o >>= 1)
            v += __shfl_xor_sync(0xffffffffu, v, o);
        if (lane == 0) ws[w] = v;
        __syncthreads();
        if (tid == 0) {
            float tot = 0.f;
            #pragma unroll
            for (int k = 0; k < 8; k++) tot += ws[k];
            out[0] = tot;
            g_cnt = 0;                     // reset for next graph replay
        }
    }
}

extern "C" void kernel_launch(void* const* d_in, const int* in_sizes, int n_in,
                              void* d_out, int out_size) {
    const float* x = (const float*)d_in[0];      // 1024x1024 row-major
    const float* w = (const float*)d_in[1];      // 30 weights
    cudaFuncSetAttribute(gemm_kernel, cudaFuncAttributeMaxDynamicSharedMemorySize, GEMM_SMEM);
    build_kernel<<<512, 512>>>(w, x);            // 256 circuit blocks + 256 y-tiles
    gemm_kernel<<<NCTA, 256, GEMM_SMEM>>>(x, (float*)d_out);
}